// round 13
// baseline (speedup 1.0000x reference)
#include <cuda_runtime.h>
#include <cstdint>
#include <math_constants.h>

#define BB 8
#define NN 16384
#define CC 256
#define HH 128
#define MM 4096
#define SS 1024

#define OFF_AGG_XYZ  0
#define OFF_AGG_FEAT 49152
#define OFF_CTR_XYZ  2146304
#define OFF_CTR_OFF  2170880
#define OFF_CTR_ORG  2195456
#define OFF_SEG      2220032

static __device__ float g_seg[BB * NN];
static __device__ int   g_fgidx[BB * MM];
static __device__ float g_fgxyz[(size_t)BB * MM * 3];
static __device__ float g_vh[(size_t)BB * HH * MM];
static __device__ float g_off[(size_t)BB * MM * 3];
static __device__ float g_cxyz[(size_t)BB * MM * 3];
static __device__ int   g_ori[BB * SS];
static __device__ int   g_ctr[BB * SS];

typedef unsigned long long u64;

__device__ __forceinline__ unsigned fkey(float s) {
    unsigned u = __float_as_uint(s);
    return (u & 0x80000000u) ? ~u : (u | 0x80000000u);
}
__device__ __forceinline__ u64 pack2(float lo, float hi) {
    u64 r; asm("mov.b64 %0, {%1, %2};" : "=l"(r) : "f"(lo), "f"(hi)); return r;
}
__device__ __forceinline__ float2 unpack2(u64 v) {
    float lo, hi; asm("mov.b64 {%0, %1}, %2;" : "=f"(lo), "=f"(hi) : "l"(v));
    return make_float2(lo, hi);
}
__device__ __forceinline__ void fma2(u64& acc, u64 a, u64 b) {
    asm("fma.rn.f32x2 %0, %1, %2, %0;" : "+l"(acc) : "l"(a), "l"(b));
}
__device__ __forceinline__ u64 add2(u64 a, u64 b) {
    u64 r; asm("add.rn.f32x2 %0, %1, %2;" : "=l"(r) : "l"(a), "l"(b)); return r;
}
__device__ __forceinline__ u64 mul2(u64 a, u64 b) {
    u64 r; asm("mul.rn.f32x2 %0, %1, %2;" : "=l"(r) : "l"(a), "l"(b)); return r;
}

// ======================= seg: S_h[b,n] = sum_o relu(sc*(W1 f)+bi) ==============
__global__ void __launch_bounds__(256, 2)
seg_kernel(const float* __restrict__ F, const float* __restrict__ W1,
           const float* __restrict__ sc, const float* __restrict__ bi)
{
    __shared__ __align__(16) float Wt[32 * 132];
    __shared__ __align__(16) float Ft[32 * 132];
    __shared__ float Pp[16 * 128];
    const int b = blockIdx.y, n0 = blockIdx.x * 128, tid = threadIdx.x;
    const int ty = tid >> 4, tx = tid & 15;
    const float* Fb = F + (size_t)b * CC * NN;

    u64 acc2[8][4];
#pragma unroll
    for (int i = 0; i < 8; i++)
#pragma unroll
        for (int j = 0; j < 4; j++) acc2[i][j] = 0ull;

    for (int ct = 0; ct < CC; ct += 32) {
        for (int i = tid; i < 4096; i += 256) {
            int o = i >> 5, c = i & 31;
            Wt[c * 132 + o] = W1[o * CC + ct + c];
        }
        for (int i = tid; i < 4096; i += 256) {
            int c = i >> 7, n = i & 127;
            Ft[c * 132 + n] = Fb[(size_t)(ct + c) * NN + n0 + n];
        }
        __syncthreads();
        const float* wp = Wt + ty * 8;
        const float* fp = Ft + tx * 8;
#pragma unroll 8
        for (int c = 0; c < 32; c++) {
            float4 a0 = *(const float4*)(wp + c * 132);
            float4 a1 = *(const float4*)(wp + c * 132 + 4);
            float4 f0 = *(const float4*)(fp + c * 132);
            float4 f1 = *(const float4*)(fp + c * 132 + 4);
            u64 bp[4] = {pack2(f0.x, f0.y), pack2(f0.z, f0.w),
                         pack2(f1.x, f1.y), pack2(f1.z, f1.w)};
            float av[8] = {a0.x, a0.y, a0.z, a0.w, a1.x, a1.y, a1.z, a1.w};
#pragma unroll
            for (int i = 0; i < 8; i++) {
                u64 ai = pack2(av[i], av[i]);
#pragma unroll
                for (int j = 0; j < 4; j++) fma2(acc2[i][j], ai, bp[j]);
            }
        }
        __syncthreads();
    }
    float s8[8];
#pragma unroll
    for (int j = 0; j < 8; j++) s8[j] = 0.f;
#pragma unroll
    for (int i = 0; i < 8; i++) {
        int o = ty * 8 + i;
        float scv = sc[o], biv = bi[o];
#pragma unroll
        for (int j = 0; j < 4; j++) {
            float2 v = unpack2(acc2[i][j]);
            s8[2 * j]     += fmaxf(fmaf(v.x, scv, biv), 0.f);
            s8[2 * j + 1] += fmaxf(fmaf(v.y, scv, biv), 0.f);
        }
    }
#pragma unroll
    for (int j = 0; j < 8; j++) Pp[ty * 128 + tx * 8 + j] = s8[j];
    __syncthreads();
    if (tid < 128) {
        float s = 0.f;
#pragma unroll
        for (int t = 0; t < 16; t++) s += Pp[t * 128 + tid];
        g_seg[b * NN + n0 + tid] = s;
    }
}

// ====== seg output (float4): seg[b,k,n] = w2[k]*S_h[b,n] + b2 ======
__global__ void __launch_bounds__(256)
segout_kernel(const float* __restrict__ w2, const float* __restrict__ b2,
              float* __restrict__ out)
{
    int n4 = blockIdx.x * 256 + threadIdx.x;
    int k = blockIdx.y, b = blockIdx.z;
    float w = w2[k], bb = b2[0];
    float4 s = *(const float4*)&g_seg[b * NN + n4 * 4];
    float4 r = make_float4(fmaf(w, s.x, bb), fmaf(w, s.y, bb),
                           fmaf(w, s.z, bb), fmaf(w, s.w, bb));
    *(float4*)&out[OFF_SEG + ((size_t)(b * 128 + k)) * NN + n4 * 4] = r;
}

// ======= top-k: register-resident keys, radix select, smem bitonic =============
__global__ void __launch_bounds__(1024, 1)
topk_kernel()
{
    __shared__ unsigned long long A[4096];
    __shared__ unsigned hist[256];
    __shared__ unsigned E[64];
    __shared__ unsigned ctrl[4];
    const int b = blockIdx.x, tid = threadIdx.x;

    unsigned key[16];
#pragma unroll
    for (int k = 0; k < 16; k++)
        key[k] = fkey(g_seg[b * NN + tid + 1024 * k]);

    unsigned prefix = 0; int rem = MM;
    for (int r = 0; r < 4; r++) {
        int shift = 24 - 8 * r;
        if (tid < 256) hist[tid] = 0;
        __syncthreads();
#pragma unroll
        for (int k = 0; k < 16; k++) {
            unsigned u = key[k];
            bool ok = (r == 0) || ((u >> (shift + 8)) == prefix);
            if (ok) atomicAdd(&hist[(u >> shift) & 255u], 1u);
        }
        __syncthreads();
        if (tid == 0) {
            int cum = 0, d = 255;
            for (;; d--) {
                if (cum + (int)hist[d] >= rem) break;
                cum += (int)hist[d];
            }
            ctrl[0] = (prefix << 8) | (unsigned)d;
            ctrl[1] = (unsigned)(rem - cum);
        }
        __syncthreads();
        prefix = ctrl[0]; rem = (int)ctrl[1];
    }
    const unsigned T = prefix;
    const int need = rem;

    if (tid == 0) { ctrl[2] = 0; ctrl[3] = 0; }
    __syncthreads();
#pragma unroll
    for (int k = 0; k < 16; k++) {
        unsigned u = key[k];
        int n = tid + 1024 * k;
        if (u > T) {
            unsigned p = atomicAdd(&ctrl[2], 1u);
            A[p] = (((unsigned long long)(~u)) << 14) | (unsigned)n;
        } else if (u == T) {
            unsigned p = atomicAdd(&ctrl[3], 1u);
            if (p < 64) E[p] = (unsigned)n;
        }
    }
    __syncthreads();
    if (tid == 0) {
        int ec = (int)ctrl[3]; if (ec > 64) ec = 64;
        for (int i = 1; i < ec; i++) {
            unsigned v = E[i]; int j = i - 1;
            while (j >= 0 && E[j] > v) { E[j + 1] = E[j]; j--; }
            E[j + 1] = v;
        }
        unsigned cnt = ctrl[2];
        for (int r = 0; r < need; r++)
            A[cnt + r] = (((unsigned long long)(~T)) << 14) | E[r];
    }
    __syncthreads();
    for (int k = 2; k <= 4096; k <<= 1) {
        for (int j = k >> 1; j > 0; j >>= 1) {
            for (int i = tid; i < 4096; i += 1024) {
                int l = i ^ j;
                if (l > i) {
                    unsigned long long a = A[i], c = A[l];
                    bool up = ((i & k) == 0);
                    if ((a > c) == up) { A[i] = c; A[l] = a; }
                }
            }
            __syncthreads();
        }
    }
    for (int m = tid; m < MM; m += 1024)
        g_fgidx[b * MM + m] = (int)(A[m] & 0x3FFFu);
}

__global__ void __launch_bounds__(256)
gatherC_kernel(const float* __restrict__ xyz)
{
    int lin = blockIdx.x * 256 + threadIdx.x;
    int b = lin >> 12, m = lin & 4095;
    int id = g_fgidx[b * MM + m];
    const float* p = xyz + ((size_t)b * NN + id) * 3;
    float* q = g_fgxyz + ((size_t)b * MM + m) * 3;
    q[0] = p[0]; q[1] = p[1]; q[2] = p[2];
}

// ======================= vote: tiled GEMM over gathered columns ================
__global__ void __launch_bounds__(256, 2)
vote_kernel(const float* __restrict__ F, const float* __restrict__ W1,
            const float* __restrict__ sc, const float* __restrict__ bi,
            const float* __restrict__ RW, const float* __restrict__ RB)
{
    __shared__ __align__(16) float pool[2 * 32 * 132];
    __shared__ int sidx[128];
    float* Wt = pool;
    float* Ft = pool + 32 * 132;
    const int b = blockIdx.y, m0 = blockIdx.x * 128, tid = threadIdx.x;
    const int ty = tid >> 4, tx = tid & 15;
    const float* Fb = F + (size_t)b * CC * NN;

    if (tid < 128) sidx[tid] = g_fgidx[b * MM + m0 + tid];
    __syncthreads();

    u64 acc2[8][4];
#pragma unroll
    for (int i = 0; i < 8; i++)
#pragma unroll
        for (int j = 0; j < 4; j++) acc2[i][j] = 0ull;

    for (int ct = 0; ct < CC; ct += 32) {
        for (int i = tid; i < 4096; i += 256) {
            int o = i >> 5, c = i & 31;
            Wt[c * 132 + o] = W1[o * CC + ct + c];
        }
        for (int i = tid; i < 4096; i += 256) {
            int c = i >> 7, j = i & 127;
            Ft[c * 132 + j] = Fb[(size_t)(ct + c) * NN + sidx[j]];
        }
        __syncthreads();
        const float* wp = Wt + ty * 8;
        const float* fp = Ft + tx * 8;
#pragma unroll 8
        for (int c = 0; c < 32; c++) {
            float4 a0 = *(const float4*)(wp + c * 132);
            float4 a1 = *(const float4*)(wp + c * 132 + 4);
            float4 f0 = *(const float4*)(fp + c * 132);
            float4 f1 = *(const float4*)(fp + c * 132 + 4);
            u64 bp[4] = {pack2(f0.x, f0.y), pack2(f0.z, f0.w),
                         pack2(f1.x, f1.y), pack2(f1.z, f1.w)};
            float av[8] = {a0.x, a0.y, a0.z, a0.w, a1.x, a1.y, a1.z, a1.w};
#pragma unroll
            for (int i = 0; i < 8; i++) {
                u64 ai = pack2(av[i], av[i]);
#pragma unroll
                for (int j = 0; j < 4; j++) fma2(acc2[i][j], ai, bp[j]);
            }
        }
        __syncthreads();
    }

    float p3[3][8] = {};
#pragma unroll
    for (int i = 0; i < 8; i++) {
        int o = ty * 8 + i;
        float scv = sc[o], biv = bi[o];
        float h[8];
#pragma unroll
        for (int j = 0; j < 4; j++) {
            float2 v = unpack2(acc2[i][j]);
            h[2 * j]     = fmaxf(fmaf(v.x, scv, biv), 0.f);
            h[2 * j + 1] = fmaxf(fmaf(v.y, scv, biv), 0.f);
        }
        float4* dst = (float4*)&g_vh[((size_t)b * HH + o) * MM + m0 + tx * 8];
        dst[0] = make_float4(h[0], h[1], h[2], h[3]);
        dst[1] = make_float4(h[4], h[5], h[6], h[7]);
#pragma unroll
        for (int k = 0; k < 3; k++) {
            float w = RW[k * HH + o];
#pragma unroll
            for (int j = 0; j < 8; j++) p3[k][j] = fmaf(w, h[j], p3[k][j]);
        }
    }
    float* red = pool;
    __syncthreads();
#pragma unroll
    for (int k = 0; k < 3; k++)
#pragma unroll
        for (int j = 0; j < 8; j++)
            red[(k * 16 + ty) * 128 + tx * 8 + j] = p3[k][j];
    __syncthreads();
    for (int t = tid; t < 384; t += 256) {
        int k = t >> 7, m = t & 127;
        float s = RB[k];
#pragma unroll
        for (int w = 0; w < 16; w++) s += red[(k * 16 + w) * 128 + m];
        float mx = (k == 2) ? 2.f : 3.f;
        s = fminf(fmaxf(s, -mx), mx);
        size_t gi = ((size_t)b * MM + m0 + m) * 3 + k;
        g_off[gi] = s;
        g_cxyz[gi] = __fadd_rn(g_fgxyz[gi], s);
    }
}

// ===== D-FPS: ONE barrier/iter — warp-local argmax, packed u64 cross-warp ======
__global__ void __launch_bounds__(256, 1)
fps_kernel()
{
    __shared__ u64 warr[2][8];
    const int blk = blockIdx.x, b = blk >> 1, which = blk & 1;
    const float* P = (which ? g_cxyz : g_fgxyz) + (size_t)b * MM * 3;
    int* out = (which ? g_ctr : g_ori) + b * SS;
    const int t = threadIdx.x;
    const int lane = t & 31, wid = t >> 5;

    u64 xp[8], yp[8], zp[8];
    float md[16];
#pragma unroll
    for (int j = 0; j < 8; j++) {
        int p0 = t + 256 * (2 * j), p1 = t + 256 * (2 * j + 1);
        xp[j] = pack2(P[p0 * 3 + 0], P[p1 * 3 + 0]);
        yp[j] = pack2(P[p0 * 3 + 1], P[p1 * 3 + 1]);
        zp[j] = pack2(P[p0 * 3 + 2], P[p1 * 3 + 2]);
        md[2 * j] = CUDART_INF_F; md[2 * j + 1] = CUDART_INF_F;
    }
    if (t == 0) out[0] = 0;
    int sp = 0, parity = 0;

    for (int i = 1; i < SS; i++) {
        float cx = __ldg(P + sp * 3 + 0);
        float cy = __ldg(P + sp * 3 + 1);
        float cz = __ldg(P + sp * 3 + 2);
        u64 ncx = pack2(-cx, -cx), ncy = pack2(-cy, -cy), ncz = pack2(-cz, -cz);
#pragma unroll
        for (int j = 0; j < 8; j++) {
            u64 dx = add2(xp[j], ncx);
            u64 dy = add2(yp[j], ncy);
            u64 dz = add2(zp[j], ncz);
            u64 s = add2(add2(mul2(dx, dx), mul2(dy, dy)), mul2(dz, dz));
            float2 d = unpack2(s);
            md[2 * j]     = fminf(md[2 * j], d.x);
            md[2 * j + 1] = fminf(md[2 * j + 1], d.y);
        }
        float m0 = fmaxf(md[0], md[1]),  m1 = fmaxf(md[2], md[3]);
        float m2 = fmaxf(md[4], md[5]),  m3 = fmaxf(md[6], md[7]);
        float m4 = fmaxf(md[8], md[9]),  m5 = fmaxf(md[10], md[11]);
        float m6 = fmaxf(md[12], md[13]), m7 = fmaxf(md[14], md[15]);
        m0 = fmaxf(m0, m1); m2 = fmaxf(m2, m3);
        m4 = fmaxf(m4, m5); m6 = fmaxf(m6, m7);
        float bv = fmaxf(fmaxf(m0, m2), fmaxf(m4, m6));

        unsigned bvb = __float_as_uint(bv);
        unsigned wm = __reduce_max_sync(0xffffffffu, bvb);   // warp max
        unsigned pos = 0xFFFFFFFFu;
        if (bvb == wm) {
            unsigned v[16];
#pragma unroll
            for (int k = 0; k < 16; k++)
                v[k] = (__float_as_uint(md[k]) == wm) ? (unsigned)(t + 256 * k)
                                                      : 0xFFFFFFFFu;
#pragma unroll
            for (int s2 = 8; s2 > 0; s2 >>= 1)
#pragma unroll
                for (int k = 0; k < 16; k++)
                    if (k < s2) v[k] = min(v[k], v[k + s2]);
            pos = v[0];
        }
        unsigned wp_ = __reduce_min_sync(0xffffffffu, pos);  // warp first-index
        if (lane == 0)
            warr[parity][wid] = (((u64)wm) << 12) | (u64)(4095u - wp_);
        __syncthreads();
        u64 sel = warr[parity][0];
#pragma unroll
        for (int w = 1; w < 8; w++) {
            u64 v = warr[parity][w];
            if (v > sel) sel = v;
        }
        sp = 4095 - (int)(sel & 0xFFFull);
        if (t == 0) out[i] = sp;
        parity ^= 1;
    }
}

// ======== final gathers: 8 h-groups x 32 s per block (more MLP) ================
__global__ void __launch_bounds__(256)
finalF_kernel(const float* __restrict__ F, float* __restrict__ out)
{
    const int b = blockIdx.y;
    const int sl = threadIdx.x & 31, hg = threadIdx.x >> 5;
    const int s = blockIdx.x * 32 + sl;
    const int ci = g_ctr[b * SS + s];
    const int oi = g_ori[b * SS + s];

    if (hg == 0) {
        const float* cvp = g_cxyz + ((size_t)b * MM + ci) * 3;
        const float* ovp = g_fgxyz + ((size_t)b * MM + oi) * 3;
        const float* fvp = g_off  + ((size_t)b * MM + ci) * 3;
        const float* gvp = g_fgxyz + ((size_t)b * MM + ci) * 3;
#pragma unroll
        for (int d = 0; d < 3; d++) {
            out[OFF_AGG_XYZ + ((size_t)b * 2048 + s) * 3 + d] = cvp[d];
            out[OFF_AGG_XYZ + ((size_t)b * 2048 + 1024 + s) * 3 + d] = ovp[d];
            out[OFF_CTR_XYZ + ((size_t)b * 1024 + s) * 3 + d] = cvp[d];
            out[OFF_CTR_OFF + ((size_t)b * 1024 + s) * 3 + d] = fvp[d];
            out[OFF_CTR_ORG + ((size_t)b * 1024 + s) * 3 + d] = gvp[d];
        }
    }
    const int gi = g_fgidx[b * MM + oi];
#pragma unroll
    for (int hh = 0; hh < 16; hh++) {
        int h = hg * 16 + hh;
        out[OFF_AGG_FEAT + ((size_t)b * HH + h) * 2048 + s] =
            g_vh[((size_t)b * HH + h) * MM + ci];
        out[OFF_AGG_FEAT + ((size_t)b * HH + h) * 2048 + 1024 + s] =
            F[((size_t)b * CC + h) * NN + gi];
    }
}

extern "C" void kernel_launch(void* const* d_in, const int* in_sizes, int n_in,
                              void* d_out, int out_size)
{
    const float* xyz  = (const float*)d_in[0];
    const float* feat = (const float*)d_in[1];
    const float* sw1  = (const float*)d_in[2];
    const float* ssc  = (const float*)d_in[3];
    const float* sbi  = (const float*)d_in[4];
    const float* sw2  = (const float*)d_in[5];
    const float* sb2  = (const float*)d_in[6];
    const float* vw1  = (const float*)d_in[7];
    const float* vsc  = (const float*)d_in[8];
    const float* vbi  = (const float*)d_in[9];
    const float* rw   = (const float*)d_in[10];
    const float* rb   = (const float*)d_in[11];
    float* out = (float*)d_out;

    seg_kernel<<<dim3(NN / 128, BB), 256>>>(feat, sw1, ssc, sbi);
    segout_kernel<<<dim3(NN / 1024, 128, BB), 256>>>(sw2, sb2, out);
    topk_kernel<<<BB, 1024>>>();
    gatherC_kernel<<<(BB * MM) / 256, 256>>>(xyz);
    vote_kernel<<<dim3(MM / 128, BB), 256>>>(feat, vw1, vsc, vbi, rw, rb);
    fps_kernel<<<2 * BB, 256>>>();
    finalF_kernel<<<dim3(SS / 32, BB), 256>>>(feat, out);
}

// round 14
// speedup vs baseline: 1.0153x; 1.0153x over previous
#include <cuda_runtime.h>
#include <cstdint>
#include <math_constants.h>

#define BB 8
#define NN 16384
#define CC 256
#define HH 128
#define MM 4096
#define SS 1024

#define OFF_AGG_XYZ  0
#define OFF_AGG_FEAT 49152
#define OFF_CTR_XYZ  2146304
#define OFF_CTR_OFF  2170880
#define OFF_CTR_ORG  2195456
#define OFF_SEG      2220032

static __device__ float g_seg[BB * NN];
static __device__ int   g_fgidx[BB * MM];
static __device__ float g_fgxyz[(size_t)BB * MM * 3];
static __device__ float g_vh[(size_t)BB * HH * MM];
static __device__ float g_off[(size_t)BB * MM * 3];
static __device__ float g_cxyz[(size_t)BB * MM * 3];
static __device__ int   g_ori[BB * SS];
static __device__ int   g_ctr[BB * SS];

typedef unsigned long long u64;

__device__ __forceinline__ unsigned fkey(float s) {
    unsigned u = __float_as_uint(s);
    return (u & 0x80000000u) ? ~u : (u | 0x80000000u);
}
__device__ __forceinline__ u64 pack2(float lo, float hi) {
    u64 r; asm("mov.b64 %0, {%1, %2};" : "=l"(r) : "f"(lo), "f"(hi)); return r;
}
__device__ __forceinline__ float2 unpack2(u64 v) {
    float lo, hi; asm("mov.b64 {%0, %1}, %2;" : "=f"(lo), "=f"(hi) : "l"(v));
    return make_float2(lo, hi);
}
__device__ __forceinline__ void fma2(u64& acc, u64 a, u64 b) {
    asm("fma.rn.f32x2 %0, %1, %2, %0;" : "+l"(acc) : "l"(a), "l"(b));
}
__device__ __forceinline__ u64 add2(u64 a, u64 b) {
    u64 r; asm("add.rn.f32x2 %0, %1, %2;" : "=l"(r) : "l"(a), "l"(b)); return r;
}
__device__ __forceinline__ u64 mul2(u64 a, u64 b) {
    u64 r; asm("mul.rn.f32x2 %0, %1, %2;" : "=l"(r) : "l"(a), "l"(b)); return r;
}

// ======================= seg: S_h[b,n] = sum_o relu(sc*(W1 f)+bi) ==============
__global__ void __launch_bounds__(256, 2)
seg_kernel(const float* __restrict__ F, const float* __restrict__ W1,
           const float* __restrict__ sc, const float* __restrict__ bi)
{
    __shared__ __align__(16) float Wt[32 * 132];
    __shared__ __align__(16) float Ft[32 * 132];
    __shared__ float Pp[16 * 128];
    const int b = blockIdx.y, n0 = blockIdx.x * 128, tid = threadIdx.x;
    const int ty = tid >> 4, tx = tid & 15;
    const float* Fb = F + (size_t)b * CC * NN;

    u64 acc2[8][4];
#pragma unroll
    for (int i = 0; i < 8; i++)
#pragma unroll
        for (int j = 0; j < 4; j++) acc2[i][j] = 0ull;

    for (int ct = 0; ct < CC; ct += 32) {
        for (int i = tid; i < 4096; i += 256) {
            int o = i >> 5, c = i & 31;
            Wt[c * 132 + o] = W1[o * CC + ct + c];
        }
        for (int i = tid; i < 4096; i += 256) {
            int c = i >> 7, n = i & 127;
            Ft[c * 132 + n] = Fb[(size_t)(ct + c) * NN + n0 + n];
        }
        __syncthreads();
        const float* wp = Wt + ty * 8;
        const float* fp = Ft + tx * 8;
#pragma unroll 8
        for (int c = 0; c < 32; c++) {
            float4 a0 = *(const float4*)(wp + c * 132);
            float4 a1 = *(const float4*)(wp + c * 132 + 4);
            float4 f0 = *(const float4*)(fp + c * 132);
            float4 f1 = *(const float4*)(fp + c * 132 + 4);
            u64 bp[4] = {pack2(f0.x, f0.y), pack2(f0.z, f0.w),
                         pack2(f1.x, f1.y), pack2(f1.z, f1.w)};
            float av[8] = {a0.x, a0.y, a0.z, a0.w, a1.x, a1.y, a1.z, a1.w};
#pragma unroll
            for (int i = 0; i < 8; i++) {
                u64 ai = pack2(av[i], av[i]);
#pragma unroll
                for (int j = 0; j < 4; j++) fma2(acc2[i][j], ai, bp[j]);
            }
        }
        __syncthreads();
    }
    float s8[8];
#pragma unroll
    for (int j = 0; j < 8; j++) s8[j] = 0.f;
#pragma unroll
    for (int i = 0; i < 8; i++) {
        int o = ty * 8 + i;
        float scv = sc[o], biv = bi[o];
#pragma unroll
        for (int j = 0; j < 4; j++) {
            float2 v = unpack2(acc2[i][j]);
            s8[2 * j]     += fmaxf(fmaf(v.x, scv, biv), 0.f);
            s8[2 * j + 1] += fmaxf(fmaf(v.y, scv, biv), 0.f);
        }
    }
#pragma unroll
    for (int j = 0; j < 8; j++) Pp[ty * 128 + tx * 8 + j] = s8[j];
    __syncthreads();
    if (tid < 128) {
        float s = 0.f;
#pragma unroll
        for (int t = 0; t < 16; t++) s += Pp[t * 128 + tid];
        g_seg[b * NN + n0 + tid] = s;
    }
}

// ====== seg output (float4): seg[b,k,n] = w2[k]*S_h[b,n] + b2 ======
__global__ void __launch_bounds__(256)
segout_kernel(const float* __restrict__ w2, const float* __restrict__ b2,
              float* __restrict__ out)
{
    int n4 = blockIdx.x * 256 + threadIdx.x;
    int k = blockIdx.y, b = blockIdx.z;
    float w = w2[k], bb = b2[0];
    float4 s = *(const float4*)&g_seg[b * NN + n4 * 4];
    float4 r = make_float4(fmaf(w, s.x, bb), fmaf(w, s.y, bb),
                           fmaf(w, s.z, bb), fmaf(w, s.w, bb));
    *(float4*)&out[OFF_SEG + ((size_t)(b * 128 + k)) * NN + n4 * 4] = r;
}

// ======= top-k: register-resident keys, radix select, smem bitonic =============
__global__ void __launch_bounds__(1024, 1)
topk_kernel()
{
    __shared__ unsigned long long A[4096];
    __shared__ unsigned hist[256];
    __shared__ unsigned E[64];
    __shared__ unsigned ctrl[4];
    const int b = blockIdx.x, tid = threadIdx.x;

    unsigned key[16];
#pragma unroll
    for (int k = 0; k < 16; k++)
        key[k] = fkey(g_seg[b * NN + tid + 1024 * k]);

    unsigned prefix = 0; int rem = MM;
    for (int r = 0; r < 4; r++) {
        int shift = 24 - 8 * r;
        if (tid < 256) hist[tid] = 0;
        __syncthreads();
#pragma unroll
        for (int k = 0; k < 16; k++) {
            unsigned u = key[k];
            bool ok = (r == 0) || ((u >> (shift + 8)) == prefix);
            if (ok) atomicAdd(&hist[(u >> shift) & 255u], 1u);
        }
        __syncthreads();
        if (tid == 0) {
            int cum = 0, d = 255;
            for (;; d--) {
                if (cum + (int)hist[d] >= rem) break;
                cum += (int)hist[d];
            }
            ctrl[0] = (prefix << 8) | (unsigned)d;
            ctrl[1] = (unsigned)(rem - cum);
        }
        __syncthreads();
        prefix = ctrl[0]; rem = (int)ctrl[1];
    }
    const unsigned T = prefix;
    const int need = rem;

    if (tid == 0) { ctrl[2] = 0; ctrl[3] = 0; }
    __syncthreads();
#pragma unroll
    for (int k = 0; k < 16; k++) {
        unsigned u = key[k];
        int n = tid + 1024 * k;
        if (u > T) {
            unsigned p = atomicAdd(&ctrl[2], 1u);
            A[p] = (((unsigned long long)(~u)) << 14) | (unsigned)n;
        } else if (u == T) {
            unsigned p = atomicAdd(&ctrl[3], 1u);
            if (p < 64) E[p] = (unsigned)n;
        }
    }
    __syncthreads();
    if (tid == 0) {
        int ec = (int)ctrl[3]; if (ec > 64) ec = 64;
        for (int i = 1; i < ec; i++) {
            unsigned v = E[i]; int j = i - 1;
            while (j >= 0 && E[j] > v) { E[j + 1] = E[j]; j--; }
            E[j + 1] = v;
        }
        unsigned cnt = ctrl[2];
        for (int r = 0; r < need; r++)
            A[cnt + r] = (((unsigned long long)(~T)) << 14) | E[r];
    }
    __syncthreads();
    for (int k = 2; k <= 4096; k <<= 1) {
        for (int j = k >> 1; j > 0; j >>= 1) {
            for (int i = tid; i < 4096; i += 1024) {
                int l = i ^ j;
                if (l > i) {
                    unsigned long long a = A[i], c = A[l];
                    bool up = ((i & k) == 0);
                    if ((a > c) == up) { A[i] = c; A[l] = a; }
                }
            }
            __syncthreads();
        }
    }
    for (int m = tid; m < MM; m += 1024)
        g_fgidx[b * MM + m] = (int)(A[m] & 0x3FFFu);
}

__global__ void __launch_bounds__(256)
gatherC_kernel(const float* __restrict__ xyz)
{
    int lin = blockIdx.x * 256 + threadIdx.x;
    int b = lin >> 12, m = lin & 4095;
    int id = g_fgidx[b * MM + m];
    const float* p = xyz + ((size_t)b * NN + id) * 3;
    float* q = g_fgxyz + ((size_t)b * MM + m) * 3;
    q[0] = p[0]; q[1] = p[1]; q[2] = p[2];
}

// ======================= vote: tiled GEMM over gathered columns ================
__global__ void __launch_bounds__(256, 2)
vote_kernel(const float* __restrict__ F, const float* __restrict__ W1,
            const float* __restrict__ sc, const float* __restrict__ bi,
            const float* __restrict__ RW, const float* __restrict__ RB)
{
    __shared__ __align__(16) float pool[2 * 32 * 132];
    __shared__ int sidx[128];
    float* Wt = pool;
    float* Ft = pool + 32 * 132;
    const int b = blockIdx.y, m0 = blockIdx.x * 128, tid = threadIdx.x;
    const int ty = tid >> 4, tx = tid & 15;
    const float* Fb = F + (size_t)b * CC * NN;

    if (tid < 128) sidx[tid] = g_fgidx[b * MM + m0 + tid];
    __syncthreads();

    u64 acc2[8][4];
#pragma unroll
    for (int i = 0; i < 8; i++)
#pragma unroll
        for (int j = 0; j < 4; j++) acc2[i][j] = 0ull;

    for (int ct = 0; ct < CC; ct += 32) {
        for (int i = tid; i < 4096; i += 256) {
            int o = i >> 5, c = i & 31;
            Wt[c * 132 + o] = W1[o * CC + ct + c];
        }
        for (int i = tid; i < 4096; i += 256) {
            int c = i >> 7, j = i & 127;
            Ft[c * 132 + j] = Fb[(size_t)(ct + c) * NN + sidx[j]];
        }
        __syncthreads();
        const float* wp = Wt + ty * 8;
        const float* fp = Ft + tx * 8;
#pragma unroll 8
        for (int c = 0; c < 32; c++) {
            float4 a0 = *(const float4*)(wp + c * 132);
            float4 a1 = *(const float4*)(wp + c * 132 + 4);
            float4 f0 = *(const float4*)(fp + c * 132);
            float4 f1 = *(const float4*)(fp + c * 132 + 4);
            u64 bp[4] = {pack2(f0.x, f0.y), pack2(f0.z, f0.w),
                         pack2(f1.x, f1.y), pack2(f1.z, f1.w)};
            float av[8] = {a0.x, a0.y, a0.z, a0.w, a1.x, a1.y, a1.z, a1.w};
#pragma unroll
            for (int i = 0; i < 8; i++) {
                u64 ai = pack2(av[i], av[i]);
#pragma unroll
                for (int j = 0; j < 4; j++) fma2(acc2[i][j], ai, bp[j]);
            }
        }
        __syncthreads();
    }

    float p3[3][8] = {};
#pragma unroll
    for (int i = 0; i < 8; i++) {
        int o = ty * 8 + i;
        float scv = sc[o], biv = bi[o];
        float h[8];
#pragma unroll
        for (int j = 0; j < 4; j++) {
            float2 v = unpack2(acc2[i][j]);
            h[2 * j]     = fmaxf(fmaf(v.x, scv, biv), 0.f);
            h[2 * j + 1] = fmaxf(fmaf(v.y, scv, biv), 0.f);
        }
        float4* dst = (float4*)&g_vh[((size_t)b * HH + o) * MM + m0 + tx * 8];
        dst[0] = make_float4(h[0], h[1], h[2], h[3]);
        dst[1] = make_float4(h[4], h[5], h[6], h[7]);
#pragma unroll
        for (int k = 0; k < 3; k++) {
            float w = RW[k * HH + o];
#pragma unroll
            for (int j = 0; j < 8; j++) p3[k][j] = fmaf(w, h[j], p3[k][j]);
        }
    }
    float* red = pool;
    __syncthreads();
#pragma unroll
    for (int k = 0; k < 3; k++)
#pragma unroll
        for (int j = 0; j < 8; j++)
            red[(k * 16 + ty) * 128 + tx * 8 + j] = p3[k][j];
    __syncthreads();
    for (int t = tid; t < 384; t += 256) {
        int k = t >> 7, m = t & 127;
        float s = RB[k];
#pragma unroll
        for (int w = 0; w < 16; w++) s += red[(k * 16 + w) * 128 + m];
        float mx = (k == 2) ? 2.f : 3.f;
        s = fminf(fmaxf(s, -mx), mx);
        size_t gi = ((size_t)b * MM + m0 + m) * 3 + k;
        g_off[gi] = s;
        g_cxyz[gi] = __fadd_rn(g_fgxyz[gi], s);
    }
}

// ===== D-FPS (R12 proven): 2 syncs/iter; selected point via uniform L1 load ====
__global__ void __launch_bounds__(256, 1)
fps_kernel()
{
    __shared__ unsigned wmax[8];
    __shared__ unsigned wpos[8];
    const int blk = blockIdx.x, b = blk >> 1, which = blk & 1;
    const float* P = (which ? g_cxyz : g_fgxyz) + (size_t)b * MM * 3;
    int* out = (which ? g_ctr : g_ori) + b * SS;
    const int t = threadIdx.x;
    const int lane = t & 31, wid = t >> 5;

    u64 xp[8], yp[8], zp[8];
    float md[16];
#pragma unroll
    for (int j = 0; j < 8; j++) {
        int p0 = t + 256 * (2 * j), p1 = t + 256 * (2 * j + 1);
        xp[j] = pack2(P[p0 * 3 + 0], P[p1 * 3 + 0]);
        yp[j] = pack2(P[p0 * 3 + 1], P[p1 * 3 + 1]);
        zp[j] = pack2(P[p0 * 3 + 2], P[p1 * 3 + 2]);
        md[2 * j] = CUDART_INF_F; md[2 * j + 1] = CUDART_INF_F;
    }
    if (t == 0) out[0] = 0;
    int sp = 0;

    for (int i = 1; i < SS; i++) {
        float cx = __ldg(P + sp * 3 + 0);
        float cy = __ldg(P + sp * 3 + 1);
        float cz = __ldg(P + sp * 3 + 2);
        u64 ncx = pack2(-cx, -cx), ncy = pack2(-cy, -cy), ncz = pack2(-cz, -cz);
#pragma unroll
        for (int j = 0; j < 8; j++) {
            u64 dx = add2(xp[j], ncx);
            u64 dy = add2(yp[j], ncy);
            u64 dz = add2(zp[j], ncz);
            u64 s = add2(add2(mul2(dx, dx), mul2(dy, dy)), mul2(dz, dz));
            float2 d = unpack2(s);
            md[2 * j]     = fminf(md[2 * j], d.x);
            md[2 * j + 1] = fminf(md[2 * j + 1], d.y);
        }
        float m0 = fmaxf(md[0], md[1]),  m1 = fmaxf(md[2], md[3]);
        float m2 = fmaxf(md[4], md[5]),  m3 = fmaxf(md[6], md[7]);
        float m4 = fmaxf(md[8], md[9]),  m5 = fmaxf(md[10], md[11]);
        float m6 = fmaxf(md[12], md[13]), m7 = fmaxf(md[14], md[15]);
        m0 = fmaxf(m0, m1); m2 = fmaxf(m2, m3);
        m4 = fmaxf(m4, m5); m6 = fmaxf(m6, m7);
        float bv = fmaxf(fmaxf(m0, m2), fmaxf(m4, m6));

        unsigned bvb = __float_as_uint(bv);
        unsigned wm = __reduce_max_sync(0xffffffffu, bvb);
        if (lane == 0) wmax[wid] = wm;
        __syncthreads();
        unsigned gm = wmax[0];
#pragma unroll
        for (int w = 1; w < 8; w++) gm = max(gm, wmax[w]);

        unsigned pos = 0xFFFFFFFFu;
        if (bvb == gm) {
            unsigned v[16];
#pragma unroll
            for (int k = 0; k < 16; k++)
                v[k] = (__float_as_uint(md[k]) == gm) ? (unsigned)(t + 256 * k)
                                                      : 0xFFFFFFFFu;
#pragma unroll
            for (int s2 = 8; s2 > 0; s2 >>= 1)
#pragma unroll
                for (int k = 0; k < 16; k++)
                    if (k < s2) v[k] = min(v[k], v[k + s2]);
            pos = v[0];
        }
        unsigned wp_ = __reduce_min_sync(0xffffffffu, pos);
        if (lane == 0) wpos[wid] = wp_;
        __syncthreads();
        unsigned spn = wpos[0];
#pragma unroll
        for (int w = 1; w < 8; w++) spn = min(spn, wpos[w]);
        sp = (int)spn;
        if (t == 0) out[i] = sp;
    }
}

// ======== final gathers (R12 proven form) ======================================
__global__ void __launch_bounds__(256)
finalF_kernel(const float* __restrict__ F, float* __restrict__ out)
{
    const int b = blockIdx.y, s = blockIdx.x * 256 + threadIdx.x;
    const int ci = g_ctr[b * SS + s];
    const int oi = g_ori[b * SS + s];
    const float* cvp = g_cxyz + ((size_t)b * MM + ci) * 3;
    const float* ovp = g_fgxyz + ((size_t)b * MM + oi) * 3;
    const float* fvp = g_off  + ((size_t)b * MM + ci) * 3;
    const float* gvp = g_fgxyz + ((size_t)b * MM + ci) * 3;
#pragma unroll
    for (int d = 0; d < 3; d++) {
        out[OFF_AGG_XYZ + ((size_t)b * 2048 + s) * 3 + d] = cvp[d];
        out[OFF_AGG_XYZ + ((size_t)b * 2048 + 1024 + s) * 3 + d] = ovp[d];
        out[OFF_CTR_XYZ + ((size_t)b * 1024 + s) * 3 + d] = cvp[d];
        out[OFF_CTR_OFF + ((size_t)b * 1024 + s) * 3 + d] = fvp[d];
        out[OFF_CTR_ORG + ((size_t)b * 1024 + s) * 3 + d] = gvp[d];
    }
    const int gi = g_fgidx[b * MM + oi];
    for (int h = 0; h < HH; h++) {
        out[OFF_AGG_FEAT + ((size_t)b * HH + h) * 2048 + s] =
            g_vh[((size_t)b * HH + h) * MM + ci];
        out[OFF_AGG_FEAT + ((size_t)b * HH + h) * 2048 + 1024 + s] =
            F[((size_t)b * CC + h) * NN + gi];
    }
}

extern "C" void kernel_launch(void* const* d_in, const int* in_sizes, int n_in,
                              void* d_out, int out_size)
{
    const float* xyz  = (const float*)d_in[0];
    const float* feat = (const float*)d_in[1];
    const float* sw1  = (const float*)d_in[2];
    const float* ssc  = (const float*)d_in[3];
    const float* sbi  = (const float*)d_in[4];
    const float* sw2  = (const float*)d_in[5];
    const float* sb2  = (const float*)d_in[6];
    const float* vw1  = (const float*)d_in[7];
    const float* vsc  = (const float*)d_in[8];
    const float* vbi  = (const float*)d_in[9];
    const float* rw   = (const float*)d_in[10];
    const float* rb   = (const float*)d_in[11];
    float* out = (float*)d_out;

    seg_kernel<<<dim3(NN / 128, BB), 256>>>(feat, sw1, ssc, sbi);
    segout_kernel<<<dim3(NN / 1024, 128, BB), 256>>>(sw2, sb2, out);
    topk_kernel<<<BB, 1024>>>();
    gatherC_kernel<<<(BB * MM) / 256, 256>>>(xyz);
    vote_kernel<<<dim3(MM / 128, BB), 256>>>(feat, vw1, vsc, vbi, rw, rb);
    fps_kernel<<<2 * BB, 256>>>();
    finalF_kernel<<<dim3(SS / 256, BB), 256>>>(feat, out);
}